// round 7
// baseline (speedup 1.0000x reference)
#include <cuda_runtime.h>

#define D_MODEL  2048
#define KV_DIM   512
#define SEQ      1024
#define BATCH    4
#define NTOK     (BATCH * SEQ)   // 4096
#define NHEADS   32
#define HEAD_DIM 64

typedef unsigned long long u64;

// ---------------- packed f32x2 helpers (Blackwell FFMA2 path) ----------------
__device__ __forceinline__ u64 pack2(float lo, float hi) {
    u64 r; asm("mov.b64 %0, {%1, %2};" : "=l"(r) : "f"(lo), "f"(hi)); return r;
}
__device__ __forceinline__ u64 bcast2(float v) {
    u64 r; asm("mov.b64 %0, {%1, %1};" : "=l"(r) : "f"(v)); return r;
}
__device__ __forceinline__ void unpack2(u64 v, float& lo, float& hi) {
    asm("mov.b64 {%0, %1}, %2;" : "=f"(lo), "=f"(hi) : "l"(v));
}
__device__ __forceinline__ void ffma2(u64& d, u64 a, u64 b) {
    asm("fma.rn.f32x2 %0, %1, %2, %0;" : "+l"(d) : "l"(a), "l"(b));
}
__device__ __forceinline__ void fmul2(u64& d, u64 a, u64 b) {
    asm("mul.rn.f32x2 %0, %1, %2;" : "=l"(d) : "l"(a), "l"(b));
}

// ---------------- scratch (no cudaMalloc allowed) ----------------
__device__ float g_q[NTOK * D_MODEL];    // 32 MB
__device__ float g_k[NTOK * KV_DIM];     //  8 MB
__device__ float g_v[NTOK * KV_DIM];     //  8 MB
__device__ float g_ctx[NTOK * D_MODEL];  // 32 MB

// ================= SGEMM: C[M,N] = A[M,K] @ B[K,N] + bias =================
// BM=BN=128, BK=16, 256 threads, 8x8 register tile, f32x2 accumulators,
// double-buffered smem with register-staged gmem prefetch.
__global__ __launch_bounds__(256) void gemm_bias_kernel(
    const float* __restrict__ A, const float* __restrict__ B,
    const float* __restrict__ bias, float* __restrict__ C,
    int N, int K)
{
    __shared__ float Ast[2][16][132];   // A tile transposed: Ast[buf][k][m]
    __shared__ float Bs[2][16][128];    // B tile natural:    Bs[buf][k][n]

    const int t  = threadIdx.x;
    const int tx = t & 15;           // 0..15 -> n
    const int ty = t >> 4;           // 0..15 -> m
    const int row0 = blockIdx.y * 128;
    const int col0 = blockIdx.x * 128;

    // per-thread gmem load coordinates (2 float4 each for A and B)
    const int ar0 = (t + 0)   >> 2, ac0 = (t + 0)   & 3;   // A: row, k-quad
    const int ar1 = (t + 256) >> 2, ac1 = (t + 256) & 3;
    const int br0 = (t + 0)   >> 5, bc0 = (t + 0)   & 31;  // B: k-row, n-quad
    const int br1 = (t + 256) >> 5, bc1 = (t + 256) & 31;

    u64 acc2[8][4];
#pragma unroll
    for (int i = 0; i < 8; i++)
#pragma unroll
        for (int j = 0; j < 4; j++) acc2[i][j] = 0ull;

    const int NT = K / 16;

    // ---- preload tile 0 directly into smem buf 0 ----
    {
        float4 a0 = *(const float4*)(A + (size_t)(row0 + ar0) * K + ac0 * 4);
        float4 a1 = *(const float4*)(A + (size_t)(row0 + ar1) * K + ac1 * 4);
        float4 b0 = *(const float4*)(B + (size_t)br0 * N + col0 + bc0 * 4);
        float4 b1 = *(const float4*)(B + (size_t)br1 * N + col0 + bc1 * 4);
        Ast[0][ac0 * 4 + 0][ar0] = a0.x; Ast[0][ac0 * 4 + 1][ar0] = a0.y;
        Ast[0][ac0 * 4 + 2][ar0] = a0.z; Ast[0][ac0 * 4 + 3][ar0] = a0.w;
        Ast[0][ac1 * 4 + 0][ar1] = a1.x; Ast[0][ac1 * 4 + 1][ar1] = a1.y;
        Ast[0][ac1 * 4 + 2][ar1] = a1.z; Ast[0][ac1 * 4 + 3][ar1] = a1.w;
        *(float4*)(&Bs[0][br0][bc0 * 4]) = b0;
        *(float4*)(&Bs[0][br1][bc1 * 4]) = b1;
    }
    __syncthreads();

    int cur = 0;
    for (int kt = 0; kt < NT; kt++) {
        // ---- prefetch tile kt+1 into registers (overlaps with compute) ----
        float4 pa0, pa1, pb0, pb1;
        const bool more = (kt + 1 < NT);
        if (more) {
            int k0 = (kt + 1) * 16;
            pa0 = *(const float4*)(A + (size_t)(row0 + ar0) * K + k0 + ac0 * 4);
            pa1 = *(const float4*)(A + (size_t)(row0 + ar1) * K + k0 + ac1 * 4);
            pb0 = *(const float4*)(B + (size_t)(k0 + br0) * N + col0 + bc0 * 4);
            pb1 = *(const float4*)(B + (size_t)(k0 + br1) * N + col0 + bc1 * 4);
        }

        // ---- compute from smem buf cur ----
#pragma unroll
        for (int kk = 0; kk < 16; kk++) {
            float a[8];
            *(float4*)(a)     = *(float4*)(&Ast[cur][kk][ty * 8]);
            *(float4*)(a + 4) = *(float4*)(&Ast[cur][kk][ty * 8 + 4]);
            float4 b0 = *(float4*)(&Bs[cur][kk][tx * 8]);
            float4 b1 = *(float4*)(&Bs[cur][kk][tx * 8 + 4]);
            u64 bb0 = pack2(b0.x, b0.y);
            u64 bb1 = pack2(b0.z, b0.w);
            u64 bb2 = pack2(b1.x, b1.y);
            u64 bb3 = pack2(b1.z, b1.w);
#pragma unroll
            for (int i = 0; i < 8; i++) {
                u64 ai = bcast2(a[i]);
                ffma2(acc2[i][0], ai, bb0);
                ffma2(acc2[i][1], ai, bb1);
                ffma2(acc2[i][2], ai, bb2);
                ffma2(acc2[i][3], ai, bb3);
            }
        }

        // ---- drain prefetch into the other buffer ----
        if (more) {
            int nxt = cur ^ 1;
            Ast[nxt][ac0 * 4 + 0][ar0] = pa0.x; Ast[nxt][ac0 * 4 + 1][ar0] = pa0.y;
            Ast[nxt][ac0 * 4 + 2][ar0] = pa0.z; Ast[nxt][ac0 * 4 + 3][ar0] = pa0.w;
            Ast[nxt][ac1 * 4 + 0][ar1] = pa1.x; Ast[nxt][ac1 * 4 + 1][ar1] = pa1.y;
            Ast[nxt][ac1 * 4 + 2][ar1] = pa1.z; Ast[nxt][ac1 * 4 + 3][ar1] = pa1.w;
            *(float4*)(&Bs[nxt][br0][bc0 * 4]) = pb0;
            *(float4*)(&Bs[nxt][br1][bc1 * 4]) = pb1;
            __syncthreads();
            cur = nxt;
        }
    }

    // ---- epilogue with bias ----
#pragma unroll
    for (int i = 0; i < 8; i++) {
        int row = row0 + ty * 8 + i;
#pragma unroll
        for (int j4 = 0; j4 < 2; j4++) {
            int col = col0 + tx * 8 + j4 * 4;
            float4 bv = *(const float4*)(bias + col);
            float c0, c1, c2, c3;
            unpack2(acc2[i][j4 * 2 + 0], c0, c1);
            unpack2(acc2[i][j4 * 2 + 1], c2, c3);
            float4 o;
            o.x = c0 + bv.x; o.y = c1 + bv.y; o.z = c2 + bv.z; o.w = c3 + bv.w;
            *(float4*)(C + (size_t)row * N + col) = o;
        }
    }
}

// ================= Flash attention (f32x2-packed) =================
// grid: (S/64, NHEADS, BATCH), 256 threads.
__global__ __launch_bounds__(256) void attn_kernel(float* __restrict__ ctx)
{
    __shared__ float Qs[64 * 64];   // Qs[r][d], pre-scaled by 1/sqrt(d)
    __shared__ float KP[64 * 64];   // phase 1: K transposed [d][c]; phase 2: P [r][c]
    __shared__ float Vs[64 * 64];   // Vs[c][d]

    const int t  = threadIdx.x;
    const int tx = t & 15;
    const int ty = t >> 4;
    const int qt = blockIdx.x;
    const int h  = blockIdx.y;
    const int b  = blockIdx.z;
    const int kvh = h >> 2;         // repeat_interleave: head h -> kv head h/4

    const float* qbase = g_q + (size_t)(b * SEQ + qt * 64) * D_MODEL + h * HEAD_DIM;
    const float* kbase = g_k + (size_t)(b * SEQ) * KV_DIM + kvh * HEAD_DIM;
    const float* vbase = g_v + (size_t)(b * SEQ) * KV_DIM + kvh * HEAD_DIM;

    // load Q tile (scaled by 0.125 = 1/sqrt(64))
#pragma unroll
    for (int it = 0; it < 4; it++) {
        int idx = t + it * 256;      // 0..1023 float4s
        int r  = idx >> 4;
        int d4 = idx & 15;
        float4 v = *(const float4*)(qbase + (size_t)r * D_MODEL + d4 * 4);
        v.x *= 0.125f; v.y *= 0.125f; v.z *= 0.125f; v.w *= 0.125f;
        *(float4*)&Qs[r * 64 + d4 * 4] = v;
    }

    float m[4], l[4];
    u64 o2[4][2];                    // output cols (tx*4+0,1) and (tx*4+2,3) packed
#pragma unroll
    for (int i = 0; i < 4; i++) {
        m[i] = -1e30f; l[i] = 0.0f;
        o2[i][0] = 0ull; o2[i][1] = 0ull;
    }

    for (int kt = 0; kt < SEQ / 64; kt++) {
        __syncthreads();   // previous-iter P/V reads done before overwrite
        const float* kb = kbase + (size_t)kt * 64 * KV_DIM;
        const float* vb = vbase + (size_t)kt * 64 * KV_DIM;
        // load K (transposed) and V tiles
#pragma unroll
        for (int it = 0; it < 4; it++) {
            int idx = t + it * 256;              // 0..1023 float4s
            int c  = idx >> 4;
            int d0 = (idx & 15) * 4;
            float4 kv4 = *(const float4*)(kb + (size_t)c * KV_DIM + d0);
            KP[(d0 + 0) * 64 + c] = kv4.x;
            KP[(d0 + 1) * 64 + c] = kv4.y;
            KP[(d0 + 2) * 64 + c] = kv4.z;
            KP[(d0 + 3) * 64 + c] = kv4.w;
            *(float4*)&Vs[c * 64 + d0] = *(const float4*)(vb + (size_t)c * KV_DIM + d0);
        }
        __syncthreads();

        // ---- scores (packed): s2[i][0]=cols tx*4+{0,1}, s2[i][1]=cols tx*4+{2,3}
        u64 s2[4][2];
#pragma unroll
        for (int i = 0; i < 4; i++) { s2[i][0] = 0ull; s2[i][1] = 0ull; }

#pragma unroll 16
        for (int d = 0; d < 64; d++) {
            float4 k4 = *(float4*)&KP[d * 64 + tx * 4];
            u64 kk0 = pack2(k4.x, k4.y);
            u64 kk1 = pack2(k4.z, k4.w);
#pragma unroll
            for (int i = 0; i < 4; i++) {
                u64 qi = bcast2(Qs[(ty * 4 + i) * 64 + d]);
                ffma2(s2[i][0], qi, kk0);
                ffma2(s2[i][1], qi, kk1);
            }
        }

        // ---- online softmax (register + shuffle over the 16 tx lanes) ----
        float p[4][4];
#pragma unroll
        for (int i = 0; i < 4; i++) {
            float s0, s1, s2f, s3;
            unpack2(s2[i][0], s0, s1);
            unpack2(s2[i][1], s2f, s3);
            float rm = fmaxf(fmaxf(s0, s1), fmaxf(s2f, s3));
#pragma unroll
            for (int off = 8; off > 0; off >>= 1)
                rm = fmaxf(rm, __shfl_xor_sync(0xffffffffu, rm, off));
            float mn   = fmaxf(m[i], rm);
            float corr = __expf(m[i] - mn);
            p[i][0] = __expf(s0 - mn);
            p[i][1] = __expf(s1 - mn);
            p[i][2] = __expf(s2f - mn);
            p[i][3] = __expf(s3 - mn);
            float rs = p[i][0] + p[i][1] + p[i][2] + p[i][3];
#pragma unroll
            for (int off = 8; off > 0; off >>= 1)
                rs += __shfl_xor_sync(0xffffffffu, rs, off);
            l[i] = l[i] * corr + rs;
            m[i] = mn;
            u64 c2 = bcast2(corr);
            fmul2(o2[i][0], o2[i][0], c2);
            fmul2(o2[i][1], o2[i][1], c2);
        }

        __syncthreads();   // everyone done reading KP as K
        // store P into KP
#pragma unroll
        for (int i = 0; i < 4; i++) {
            float4 pv;
            pv.x = p[i][0]; pv.y = p[i][1]; pv.z = p[i][2]; pv.w = p[i][3];
            *(float4*)&KP[(ty * 4 + i) * 64 + tx * 4] = pv;
        }
        __syncthreads();

        // ---- O += P @ V (packed) ----
#pragma unroll 16
        for (int c = 0; c < 64; c++) {
            float4 v4 = *(float4*)&Vs[c * 64 + tx * 4];
            u64 vv0 = pack2(v4.x, v4.y);
            u64 vv1 = pack2(v4.z, v4.w);
#pragma unroll
            for (int i = 0; i < 4; i++) {
                u64 pi = bcast2(KP[(ty * 4 + i) * 64 + c]);
                ffma2(o2[i][0], pi, vv0);
                ffma2(o2[i][1], pi, vv1);
            }
        }
    }

    // ---- write ctx in [B, S, H*d] layout ----
    float* cb = ctx + (size_t)(b * SEQ + qt * 64) * D_MODEL + h * HEAD_DIM;
#pragma unroll
    for (int i = 0; i < 4; i++) {
        float inv = 1.0f / l[i];
        float o0, o1, o2f, o3;
        unpack2(o2[i][0], o0, o1);
        unpack2(o2[i][1], o2f, o3);
        float4 ov;
        ov.x = o0 * inv; ov.y = o1 * inv; ov.z = o2f * inv; ov.w = o3 * inv;
        *(float4*)(cb + (size_t)(ty * 4 + i) * D_MODEL + tx * 4) = ov;
    }
}

// ================= launch =================
extern "C" void kernel_launch(void* const* d_in, const int* in_sizes, int n_in,
                              void* d_out, int out_size)
{
    const float* x  = (const float*)d_in[0];
    const float* Wq = (const float*)d_in[1];
    const float* bq = (const float*)d_in[2];
    const float* Wk = (const float*)d_in[3];
    const float* bk = (const float*)d_in[4];
    const float* Wv = (const float*)d_in[5];
    const float* bv = (const float*)d_in[6];
    const float* Wo = (const float*)d_in[7];
    const float* bo = (const float*)d_in[8];
    float* out = (float*)d_out;

    float *qb, *kb, *vb, *cb;
    cudaGetSymbolAddress((void**)&qb, g_q);
    cudaGetSymbolAddress((void**)&kb, g_k);
    cudaGetSymbolAddress((void**)&vb, g_v);
    cudaGetSymbolAddress((void**)&cb, g_ctx);

    dim3 blk(256);
    // projections
    gemm_bias_kernel<<<dim3(D_MODEL / 128, NTOK / 128), blk>>>(x, Wq, bq, qb, D_MODEL, D_MODEL);
    gemm_bias_kernel<<<dim3(KV_DIM  / 128, NTOK / 128), blk>>>(x, Wk, bk, kb, KV_DIM,  D_MODEL);
    gemm_bias_kernel<<<dim3(KV_DIM  / 128, NTOK / 128), blk>>>(x, Wv, bv, vb, KV_DIM,  D_MODEL);
    // attention
    attn_kernel<<<dim3(SEQ / 64, NHEADS, BATCH), blk>>>(cb);
    // output projection
    gemm_bias_kernel<<<dim3(D_MODEL / 128, NTOK / 128), blk>>>(cb, Wo, bo, out, D_MODEL, D_MODEL);
}

// round 16
// speedup vs baseline: 1.6084x; 1.6084x over previous
#include <cuda_runtime.h>
#include <cuda_bf16.h>
#include <cstdint>

#define D_MODEL  2048
#define KV_DIM   512
#define SEQ      1024
#define BATCH    4
#define NTOK     (BATCH * SEQ)   // 4096
#define NHEADS   32
#define HEAD_DIM 64
#define GK       D_MODEL         // inner K of all projections (2048)

typedef unsigned long long u64;
typedef unsigned int u32;

// ---------------- packed f32x2 helpers (attn kernel) ----------------
__device__ __forceinline__ u64 pack2(float lo, float hi) {
    u64 r; asm("mov.b64 %0, {%1, %2};" : "=l"(r) : "f"(lo), "f"(hi)); return r;
}
__device__ __forceinline__ u64 bcast2(float v) {
    u64 r; asm("mov.b64 %0, {%1, %1};" : "=l"(r) : "f"(v)); return r;
}
__device__ __forceinline__ void unpack2(u64 v, float& lo, float& hi) {
    asm("mov.b64 {%0, %1}, %2;" : "=f"(lo), "=f"(hi) : "l"(v));
}
__device__ __forceinline__ void ffma2(u64& d, u64 a, u64 b) {
    asm("fma.rn.f32x2 %0, %1, %2, %0;" : "+l"(d) : "l"(a), "l"(b));
}
__device__ __forceinline__ void fmul2(u64& d, u64 a, u64 b) {
    asm("mul.rn.f32x2 %0, %1, %2;" : "=l"(d) : "l"(a), "l"(b));
}

__device__ __forceinline__ u32 s2u(const void* p) {
    u32 a; asm("{ .reg .u64 t; cvta.to.shared.u64 t, %1; cvt.u32.u64 %0, t; }" : "=r"(a) : "l"(p));
    return a;
}

// ---------------- scratch (no cudaMalloc allowed) ----------------
__device__ float g_q[NTOK * D_MODEL];
__device__ float g_k[NTOK * KV_DIM];
__device__ float g_v[NTOK * KV_DIM];
__device__ float g_ctx[NTOK * D_MODEL];
// bf16 hi/lo operands
__device__ __nv_bfloat16 g_xhi[NTOK * GK],  g_xlo[NTOK * GK];
__device__ __nv_bfloat16 g_chi[NTOK * GK],  g_clo[NTOK * GK];
__device__ __nv_bfloat16 g_wqhi[D_MODEL * GK], g_wqlo[D_MODEL * GK];   // [N][K]
__device__ __nv_bfloat16 g_wkhi[KV_DIM * GK],  g_wklo[KV_DIM * GK];
__device__ __nv_bfloat16 g_wvhi[KV_DIM * GK],  g_wvlo[KV_DIM * GK];
__device__ __nv_bfloat16 g_wohi[D_MODEL * GK], g_wolo[D_MODEL * GK];

// ================= fp32 -> bf16 hi/lo (elementwise, same layout) =================
__global__ __launch_bounds__(256) void convpair_kernel(
    const float* __restrict__ X, __nv_bfloat16* __restrict__ H, __nv_bfloat16* __restrict__ L)
{
    int i = blockIdx.x * 256 + threadIdx.x;         // float2 index
    float2 v = ((const float2*)X)[i];
    __nv_bfloat16 hx = __float2bfloat16(v.x);
    __nv_bfloat16 hy = __float2bfloat16(v.y);
    __nv_bfloat162 h2; h2.x = hx; h2.y = hy;
    __nv_bfloat162 l2;
    l2.x = __float2bfloat16(v.x - __bfloat162float(hx));
    l2.y = __float2bfloat16(v.y - __bfloat162float(hy));
    ((__nv_bfloat162*)H)[i] = h2;
    ((__nv_bfloat162*)L)[i] = l2;
}

// ================= W[K][Nw] fp32 -> transposed bf16 hi/lo [Nw][K] =================
__global__ __launch_bounds__(256) void convw_kernel(
    const float* __restrict__ W, __nv_bfloat16* __restrict__ Th, __nv_bfloat16* __restrict__ Tl, int Nw)
{
    __shared__ float tile[32][33];
    const int tx = threadIdx.x, ty = threadIdx.y;
    const int n0 = blockIdx.x * 32, k0 = blockIdx.y * 32;
#pragma unroll
    for (int r = ty; r < 32; r += 8)
        tile[r][tx] = W[(size_t)(k0 + r) * Nw + n0 + tx];
    __syncthreads();
#pragma unroll
    for (int r = ty; r < 32; r += 8) {
        float v = tile[tx][r];                       // = W[k0+tx][n0+r]
        __nv_bfloat16 h = __float2bfloat16(v);
        size_t o = (size_t)(n0 + r) * GK + k0 + tx;
        Th[o] = h;
        Tl[o] = __float2bfloat16(v - __bfloat162float(h));
    }
}

// ================= mma.sync bf16-split GEMM =================
// C[M,N] = Ahi*Bhi + Alo*Bhi + Ahi*Blo (+bias), A:[M][GK] K-major, B:[N][GK] K-major.
// CTA 128x128 tile, 8 warps (2 M x 4 N), warp tile 64x32. K chunks of 32,
// cp.async double-buffered smem. Padded 80B rows -> conflict-free ldmatrix.
#define KC     32
#define NCH    (GK / KC)          // 64
#define LDAH   40                 // bf16 elems per smem row (80 B)
#define MAT_B  (128 * LDAH * 2)   // 10240 B per matrix (Ahi/Alo/Bhi/Blo)
#define BUF_B  (4 * MAT_B)        // 40960 B per k-chunk buffer
#define SMEM_TC (2 * BUF_B)       // 81920 B

__global__ __launch_bounds__(256) void gemm_tc_kernel(
    const __nv_bfloat16* __restrict__ Ahi, const __nv_bfloat16* __restrict__ Alo,
    const __nv_bfloat16* __restrict__ Bhi, const __nv_bfloat16* __restrict__ Blo,
    const float* __restrict__ bias, float* __restrict__ C, int N)
{
    extern __shared__ char sm[];
    const int t    = threadIdx.x;
    const int lane = t & 31;
    const int w    = t >> 5;
    const int wm   = w & 1;        // 0..1 -> M group of 64
    const int wn   = w >> 1;       // 0..3 -> N group of 32
    const int row0 = blockIdx.y * 128;
    const int col0 = blockIdx.x * 128;
    const u32 sb   = s2u(sm);

    float acc[4][4][4];
#pragma unroll
    for (int mt = 0; mt < 4; mt++)
#pragma unroll
        for (int nt = 0; nt < 4; nt++)
#pragma unroll
            for (int j = 0; j < 4; j++) acc[mt][nt][j] = 0.0f;

    // ---- async loader: chunk c -> buffer buf ----
    auto load_chunk = [&](int c, int buf) {
        const int k0 = c * KC;
        const u32 dbase = sb + (u32)buf * BUF_B;
#pragma unroll
        for (int it = 0; it < 8; it++) {
            int u   = t + it * 256;          // 0..2047 16B-chunks
            int mat = u >> 9;                // 0..3
            int r   = (u >> 2) & 127;
            int q   = u & 3;
            const __nv_bfloat16* src;
            if (mat == 0)      src = Ahi + (size_t)(row0 + r) * GK + k0 + q * 8;
            else if (mat == 1) src = Alo + (size_t)(row0 + r) * GK + k0 + q * 8;
            else if (mat == 2) src = Bhi + (size_t)(col0 + r) * GK + k0 + q * 8;
            else               src = Blo + (size_t)(col0 + r) * GK + k0 + q * 8;
            u32 dst = dbase + (u32)(mat * MAT_B + r * (LDAH * 2) + q * 16);
            u64 gsrc = (u64)__cvta_generic_to_global(src);
            asm volatile("cp.async.ca.shared.global [%0], [%1], 16;" :: "r"(dst), "l"(gsrc) : "memory");
        }
        asm volatile("cp.async.commit_group;" ::: "memory");
    };

    load_chunk(0, 0);

    for (int c = 0; c < NCH; c++) {
        if (c + 1 < NCH) {
            load_chunk(c + 1, (c + 1) & 1);
            asm volatile("cp.async.wait_group 1;" ::: "memory");
        } else {
            asm volatile("cp.async.wait_group 0;" ::: "memory");
        }
        __syncthreads();

        const u32 bb = sb + (u32)(c & 1) * BUF_B;
#pragma unroll
        for (int ks = 0; ks < 2; ks++) {
            // ---- B fragments (hi & lo) for all 4 n-tiles ----
            // [N][K] K-contiguous smem + row.col mma  =>  NON-trans ldmatrix:
            // lane i holds fixed n=i/4 with consecutive k-pairs.
            u32 bh[4][2], bl[4][2];
            const int l16 = lane & 15;
#pragma unroll
            for (int nt = 0; nt < 4; nt++) {
                u32 ba = bb + (u32)(2 * MAT_B +
                          (wn * 32 + nt * 8 + (l16 & 7)) * (LDAH * 2) +
                          (ks * 16 + (l16 >> 3) * 8) * 2);
                asm volatile("ldmatrix.sync.aligned.m8n8.x2.shared.b16 {%0,%1}, [%2];"
                             : "=r"(bh[nt][0]), "=r"(bh[nt][1]) : "r"(ba));
                asm volatile("ldmatrix.sync.aligned.m8n8.x2.shared.b16 {%0,%1}, [%2];"
                             : "=r"(bl[nt][0]), "=r"(bl[nt][1]) : "r"(ba + MAT_B));
            }
#pragma unroll
            for (int mt = 0; mt < 4; mt++) {
                u32 aa = bb + (u32)((wm * 64 + mt * 16 + (lane & 15)) * (LDAH * 2) +
                                    (ks * 16 + (lane >> 4) * 8) * 2);
                u32 ah[4], al[4];
                asm volatile("ldmatrix.sync.aligned.m8n8.x4.shared.b16 {%0,%1,%2,%3}, [%4];"
                             : "=r"(ah[0]), "=r"(ah[1]), "=r"(ah[2]), "=r"(ah[3]) : "r"(aa));
                asm volatile("ldmatrix.sync.aligned.m8n8.x4.shared.b16 {%0,%1,%2,%3}, [%4];"
                             : "=r"(al[0]), "=r"(al[1]), "=r"(al[2]), "=r"(al[3]) : "r"(aa + MAT_B));
#pragma unroll
                for (int nt = 0; nt < 4; nt++) {
                    float* d = acc[mt][nt];
                    asm volatile("mma.sync.aligned.m16n8k16.row.col.f32.bf16.bf16.f32 "
                        "{%0,%1,%2,%3}, {%4,%5,%6,%7}, {%8,%9}, {%0,%1,%2,%3};"
                        : "+f"(d[0]), "+f"(d[1]), "+f"(d[2]), "+f"(d[3])
                        : "r"(ah[0]), "r"(ah[1]), "r"(ah[2]), "r"(ah[3]), "r"(bh[nt][0]), "r"(bh[nt][1]));
                    asm volatile("mma.sync.aligned.m16n8k16.row.col.f32.bf16.bf16.f32 "
                        "{%0,%1,%2,%3}, {%4,%5,%6,%7}, {%8,%9}, {%0,%1,%2,%3};"
                        : "+f"(d[0]), "+f"(d[1]), "+f"(d[2]), "+f"(d[3])
                        : "r"(al[0]), "r"(al[1]), "r"(al[2]), "r"(al[3]), "r"(bh[nt][0]), "r"(bh[nt][1]));
                    asm volatile("mma.sync.aligned.m16n8k16.row.col.f32.bf16.bf16.f32 "
                        "{%0,%1,%2,%3}, {%4,%5,%6,%7}, {%8,%9}, {%0,%1,%2,%3};"
                        : "+f"(d[0]), "+f"(d[1]), "+f"(d[2]), "+f"(d[3])
                        : "r"(ah[0]), "r"(ah[1]), "r"(ah[2]), "r"(ah[3]), "r"(bl[nt][0]), "r"(bl[nt][1]));
                }
            }
        }
        __syncthreads();
    }

    // ---- epilogue with bias ----
    const int gid  = lane >> 2;    // 0..7 (row within m16 half)
    const int tid4 = lane & 3;     // col pair
#pragma unroll
    for (int mt = 0; mt < 4; mt++) {
        int row_a = row0 + wm * 64 + mt * 16 + gid;
        int row_b = row_a + 8;
#pragma unroll
        for (int nt = 0; nt < 4; nt++) {
            int col = col0 + wn * 32 + nt * 8 + tid4 * 2;
            float2 bv = *(const float2*)(bias + col);
            float2 o0, o1;
            o0.x = acc[mt][nt][0] + bv.x; o0.y = acc[mt][nt][1] + bv.y;
            o1.x = acc[mt][nt][2] + bv.x; o1.y = acc[mt][nt][3] + bv.y;
            *(float2*)(C + (size_t)row_a * N + col) = o0;
            *(float2*)(C + (size_t)row_b * N + col) = o1;
        }
    }
}

// ================= Flash attention (unchanged, known-passing) =================
__global__ __launch_bounds__(256) void attn_kernel(float* __restrict__ ctx)
{
    __shared__ float Qs[64 * 64];
    __shared__ float KP[64 * 64];
    __shared__ float Vs[64 * 64];

    const int t  = threadIdx.x;
    const int tx = t & 15;
    const int ty = t >> 4;
    const int qt = blockIdx.x;
    const int h  = blockIdx.y;
    const int b  = blockIdx.z;
    const int kvh = h >> 2;

    const float* qbase = g_q + (size_t)(b * SEQ + qt * 64) * D_MODEL + h * HEAD_DIM;
    const float* kbase = g_k + (size_t)(b * SEQ) * KV_DIM + kvh * HEAD_DIM;
    const float* vbase = g_v + (size_t)(b * SEQ) * KV_DIM + kvh * HEAD_DIM;

#pragma unroll
    for (int it = 0; it < 4; it++) {
        int idx = t + it * 256;
        int r  = idx >> 4;
        int d4 = idx & 15;
        float4 v = *(const float4*)(qbase + (size_t)r * D_MODEL + d4 * 4);
        v.x *= 0.125f; v.y *= 0.125f; v.z *= 0.125f; v.w *= 0.125f;
        *(float4*)&Qs[r * 64 + d4 * 4] = v;
    }

    float m[4], l[4];
    u64 o2[4][2];
#pragma unroll
    for (int i = 0; i < 4; i++) {
        m[i] = -1e30f; l[i] = 0.0f;
        o2[i][0] = 0ull; o2[i][1] = 0ull;
    }

    for (int kt = 0; kt < SEQ / 64; kt++) {
        __syncthreads();
        const float* kb = kbase + (size_t)kt * 64 * KV_DIM;
        const float* vb = vbase + (size_t)kt * 64 * KV_DIM;
#pragma unroll
        for (int it = 0; it < 4; it++) {
            int idx = t + it * 256;
            int c  = idx >> 4;
            int d0 = (idx & 15) * 4;
            float4 kv4 = *(const float4*)(kb + (size_t)c * KV_DIM + d0);
            KP[(d0 + 0) * 64 + c] = kv4.x;
            KP[(d0 + 1) * 64 + c] = kv4.y;
            KP[(d0 + 2) * 64 + c] = kv4.z;
            KP[(d0 + 3) * 64 + c] = kv4.w;
            *(float4*)&Vs[c * 64 + d0] = *(const float4*)(vb + (size_t)c * KV_DIM + d0);
        }
        __syncthreads();

        u64 s2[4][2];
#pragma unroll
        for (int i = 0; i < 4; i++) { s2[i][0] = 0ull; s2[i][1] = 0ull; }

#pragma unroll 16
        for (int d = 0; d < 64; d++) {
            float4 k4 = *(float4*)&KP[d * 64 + tx * 4];
            u64 kk0 = pack2(k4.x, k4.y);
            u64 kk1 = pack2(k4.z, k4.w);
#pragma unroll
            for (int i = 0; i < 4; i++) {
                u64 qi = bcast2(Qs[(ty * 4 + i) * 64 + d]);
                ffma2(s2[i][0], qi, kk0);
                ffma2(s2[i][1], qi, kk1);
            }
        }

        float p[4][4];
#pragma unroll
        for (int i = 0; i < 4; i++) {
            float s0, s1, s2f, s3;
            unpack2(s2[i][0], s0, s1);
            unpack2(s2[i][1], s2f, s3);
            float rm = fmaxf(fmaxf(s0, s1), fmaxf(s2f, s3));
#pragma unroll
            for (int off = 8; off > 0; off >>= 1)
                rm = fmaxf(rm, __shfl_xor_sync(0xffffffffu, rm, off));
            float mn   = fmaxf(m[i], rm);
            float corr = __expf(m[i] - mn);
            p[i][0] = __expf(s0 - mn);
            p[i][1] = __expf(s1 - mn);
            p[i][2] = __expf(s2f - mn);
            p[i][3] = __expf(s3 - mn);
            float rs = p[i][0] + p[i][1] + p[i][2] + p[i][3];
#pragma unroll
            for (int off = 8; off > 0; off >>= 1)
                rs += __shfl_xor_sync(0xffffffffu, rs, off);
            l[i] = l[i] * corr + rs;
            m[i] = mn;
            u64 c2 = bcast2(corr);
            fmul2(o2[i][0], o2[i][0], c2);
            fmul2(o2[i][1], o2[i][1], c2);
        }

        __syncthreads();
#pragma unroll
        for (int i = 0; i < 4; i++) {
            float4 pv;
            pv.x = p[i][0]; pv.y = p[i][1]; pv.z = p[i][2]; pv.w = p[i][3];
            *(float4*)&KP[(ty * 4 + i) * 64 + tx * 4] = pv;
        }
        __syncthreads();

#pragma unroll 16
        for (int c = 0; c < 64; c++) {
            float4 v4 = *(float4*)&Vs[c * 64 + tx * 4];
            u64 vv0 = pack2(v4.x, v4.y);
            u64 vv1 = pack2(v4.z, v4.w);
#pragma unroll
            for (int i = 0; i < 4; i++) {
                u64 pi = bcast2(KP[(ty * 4 + i) * 64 + c]);
                ffma2(o2[i][0], pi, vv0);
                ffma2(o2[i][1], pi, vv1);
            }
        }
    }

    float* cb = ctx + (size_t)(b * SEQ + qt * 64) * D_MODEL + h * HEAD_DIM;
#pragma unroll
    for (int i = 0; i < 4; i++) {
        float inv = 1.0f / l[i];
        float o0, o1, o2f, o3;
        unpack2(o2[i][0], o0, o1);
        unpack2(o2[i][1], o2f, o3);
        float4 ov;
        ov.x = o0 * inv; ov.y = o1 * inv; ov.z = o2f * inv; ov.w = o3 * inv;
        *(float4*)(cb + (size_t)(ty * 4 + i) * D_MODEL + tx * 4) = ov;
    }
}

// ================= launch =================
extern "C" void kernel_launch(void* const* d_in, const int* in_sizes, int n_in,
                              void* d_out, int out_size)
{
    const float* x  = (const float*)d_in[0];
    const float* Wq = (const float*)d_in[1];
    const float* bq = (const float*)d_in[2];
    const float* Wk = (const float*)d_in[3];
    const float* bk = (const float*)d_in[4];
    const float* Wv = (const float*)d_in[5];
    const float* bv = (const float*)d_in[6];
    const float* Wo = (const float*)d_in[7];
    const float* bo = (const float*)d_in[8];
    float* out = (float*)d_out;

    float *qb, *kb, *vb, *cb;
    cudaGetSymbolAddress((void**)&qb, g_q);
    cudaGetSymbolAddress((void**)&kb, g_k);
    cudaGetSymbolAddress((void**)&vb, g_v);
    cudaGetSymbolAddress((void**)&cb, g_ctx);
    __nv_bfloat16 *xhi, *xlo, *chi, *clo, *wqh, *wql, *wkh, *wkl, *wvh, *wvl, *woh, *wol;
    cudaGetSymbolAddress((void**)&xhi, g_xhi);  cudaGetSymbolAddress((void**)&xlo, g_xlo);
    cudaGetSymbolAddress((void**)&chi, g_chi);  cudaGetSymbolAddress((void**)&clo, g_clo);
    cudaGetSymbolAddress((void**)&wqh, g_wqhi); cudaGetSymbolAddress((void**)&wql, g_wqlo);
    cudaGetSymbolAddress((void**)&wkh, g_wkhi); cudaGetSymbolAddress((void**)&wkl, g_wklo);
    cudaGetSymbolAddress((void**)&wvh, g_wvhi); cudaGetSymbolAddress((void**)&wvl, g_wvlo);
    cudaGetSymbolAddress((void**)&woh, g_wohi); cudaGetSymbolAddress((void**)&wol, g_wolo);

    cudaFuncSetAttribute(gemm_tc_kernel, cudaFuncAttributeMaxDynamicSharedMemorySize, SMEM_TC);

    // ---- convert inputs to bf16 hi/lo ----
    convpair_kernel<<<NTOK * D_MODEL / 512, 256>>>(x, xhi, xlo);
    convw_kernel<<<dim3(D_MODEL / 32, D_MODEL / 32), dim3(32, 8)>>>(Wq, wqh, wql, D_MODEL);
    convw_kernel<<<dim3(KV_DIM  / 32, D_MODEL / 32), dim3(32, 8)>>>(Wk, wkh, wkl, KV_DIM);
    convw_kernel<<<dim3(KV_DIM  / 32, D_MODEL / 32), dim3(32, 8)>>>(Wv, wvh, wvl, KV_DIM);
    convw_kernel<<<dim3(D_MODEL / 32, D_MODEL / 32), dim3(32, 8)>>>(Wo, woh, wol, D_MODEL);

    // ---- projections on tensor cores (mma.sync bf16 split) ----
    gemm_tc_kernel<<<dim3(D_MODEL / 128, NTOK / 128), 256, SMEM_TC>>>(xhi, xlo, wqh, wql, bq, qb, D_MODEL);
    gemm_tc_kernel<<<dim3(KV_DIM  / 128, NTOK / 128), 256, SMEM_TC>>>(xhi, xlo, wkh, wkl, bk, kb, KV_DIM);
    gemm_tc_kernel<<<dim3(KV_DIM  / 128, NTOK / 128), 256, SMEM_TC>>>(xhi, xlo, wvh, wvl, bv, vb, KV_DIM);

    // ---- attention (scalar fp32, unchanged) ----
    attn_kernel<<<dim3(SEQ / 64, NHEADS, BATCH), 256>>>(cb);

    // ---- output projection ----
    convpair_kernel<<<NTOK * D_MODEL / 512, 256>>>(cb, chi, clo);
    gemm_tc_kernel<<<dim3(D_MODEL / 128, NTOK / 128), 256, SMEM_TC>>>(chi, clo, woh, wol, bo, out, D_MODEL);
}